// round 7
// baseline (speedup 1.0000x reference)
#include <cuda_runtime.h>
#include <cstdint>
#include <math.h>

#define EMBED   2048
#define NEXP    64
#define TOPK    8
#define BM      128
#define BK      32
#define NCHUNK  (EMBED / BK)     // 64
#define STAGE_F 6144             // floats per stage: A 4096 + B 2048
#define BOFF    4096             // B region offset within a stage (floats)
#define DELTA   2e-4f            // near-tie threshold (score err ~1e-5 << DELTA/2)

// smem float-index map (total 12288 floats = 48 KB):
//   0..8191    score rows (epilogue) / GEMM stages (mainloop)
//   8704..8767 bias
//   8768..8895 64 doubles (fp64 rescore)
//   8896..9023 flag list (int)
//   9024       flag count (int)

// ---- mma.sync m16n8k8 row.col f32.tf32.tf32.f32 (compute_103-legal) ----
__device__ __forceinline__ void mma8(float* c,
                                     uint32_t a0, uint32_t a1, uint32_t a2, uint32_t a3,
                                     uint32_t b0, uint32_t b1) {
    asm volatile(
        "mma.sync.aligned.m16n8k8.row.col.f32.tf32.tf32.f32 "
        "{%0,%1,%2,%3}, {%4,%5,%6,%7}, {%8,%9}, {%0,%1,%2,%3};"
        : "+f"(c[0]), "+f"(c[1]), "+f"(c[2]), "+f"(c[3])
        : "r"(a0), "r"(a1), "r"(a2), "r"(a3), "r"(b0), "r"(b1));
}

// exact fp32 -> round-nearest tf32 hi + exact residual lo (x == hi + lo)
__device__ __forceinline__ void split1(uint32_t xb, uint32_t& h, uint32_t& l) {
    float x = __uint_as_float(xb);
    uint32_t hb;
    asm("cvt.rna.tf32.f32 %0, %1;" : "=r"(hb) : "f"(x));
    h = hb;
    l = __float_as_uint(x - __uint_as_float(hb));
}

__global__ __launch_bounds__(256, 2)
void router_mma(const float* __restrict__ X,
                const float* __restrict__ W,
                const float* __restrict__ bias,
                float* __restrict__ out,
                int M, int write_idx)
{
    __shared__ float sm[2 * STAGE_F];        // 48 KB exactly
    const int tid  = threadIdx.x;
    const int lane = tid & 31;
    const int wid  = tid >> 5;
    const int m0   = blockIdx.x * BM;

    // ---------- producer decode (all 256 threads) ----------
    const int pmi = tid >> 5;
    const int pg  = (tid >> 2) & 7;
    const int pki = tid & 3;

    const float* xp = X + (size_t)(m0 + pmi * 16 + pg) * EMBED + pki * 8;
    const float* wp = W + (size_t)(pmi * 8 + pg) * EMBED + pki * 8;

    const int fbA = pmi * 4 + pki;
    int stsA[4];
    #pragma unroll
    for (int t = 0; t < 4; t++)
        stsA[t] = fbA * 128 + (((pg * 4 + t) ^ ((pmi & 1) * 4 + pki)) * 4);
    const int stsB = BOFF + (pki * 8 + pmi) * 64 + (pg ^ ((pki * 5) & 7)) * 8;

    // ---------- consumer decode ----------
    const int cmi = wid;
    const int cg  = lane >> 2;
    const int ct  = lane & 3;

    float acc[8][4];
    #pragma unroll
    for (int i = 0; i < 8; i++) { acc[i][0] = acc[i][1] = acc[i][2] = acc[i][3] = 0.f; }

    float4 a00, a01, a10, a11, bb0, bb1;
    a00 = *(const float4*)(xp);
    a01 = *(const float4*)(xp + 4);
    a10 = *(const float4*)(xp + 8 * EMBED);
    a11 = *(const float4*)(xp + 8 * EMBED + 4);
    bb0 = *(const float4*)(wp);
    bb1 = *(const float4*)(wp + 4);
    {
        float* so = sm;
        *(float4*)(so + stsA[0]) = make_float4(a00.x, a10.x, a01.x, a11.x);
        *(float4*)(so + stsA[1]) = make_float4(a00.y, a10.y, a01.y, a11.y);
        *(float4*)(so + stsA[2]) = make_float4(a00.z, a10.z, a01.z, a11.z);
        *(float4*)(so + stsA[3]) = make_float4(a00.w, a10.w, a01.w, a11.w);
        *(float4*)(so + stsB)     = make_float4(bb0.x, bb1.x, bb0.y, bb1.y);
        *(float4*)(so + stsB + 4) = make_float4(bb0.z, bb1.z, bb0.w, bb1.w);
    }

    for (int c = 0; c < NCHUNK; c++) {
        const float* sb = sm + (c & 1) * STAGE_F;
        if (c + 1 < NCHUNK) {
            const float* xq = xp + (c + 1) * BK;
            const float* wq = wp + (c + 1) * BK;
            a00 = *(const float4*)(xq);
            a01 = *(const float4*)(xq + 4);
            a10 = *(const float4*)(xq + 8 * EMBED);
            a11 = *(const float4*)(xq + 8 * EMBED + 4);
            bb0 = *(const float4*)(wq);
            bb1 = *(const float4*)(wq + 4);
        }
        __syncthreads();

        #pragma unroll
        for (int ki = 0; ki < 4; ki++) {
            const int fb = cmi * 4 + ki;
            const uint4 av = *(const uint4*)(sb + fb * 128 + ((lane ^ (fb & 7)) * 4));
            uint32_t ah[4], al[4];
            split1(av.x, ah[0], al[0]); split1(av.y, ah[1], al[1]);
            split1(av.z, ah[2], al[2]); split1(av.w, ah[3], al[3]);
            const int bsw = ((cg ^ ((ki * 5) & 7)) * 4 + ct) * 2;
            #pragma unroll
            for (int ni = 0; ni < 8; ni++) {
                const float2 bv = *(const float2*)(sb + BOFF + (ki * 8 + ni) * 64 + bsw);
                uint32_t bh0, bl0, bh1, bl1;
                split1(__float_as_uint(bv.x), bh0, bl0);
                split1(__float_as_uint(bv.y), bh1, bl1);
                mma8(acc[ni], ah[0], ah[1], ah[2], ah[3], bh0, bh1);
                mma8(acc[ni], ah[0], ah[1], ah[2], ah[3], bl0, bl1);
                mma8(acc[ni], al[0], al[1], al[2], al[3], bh0, bh1);
            }
        }

        if (c + 1 < NCHUNK) {
            float* so = sm + ((c + 1) & 1) * STAGE_F;
            *(float4*)(so + stsA[0]) = make_float4(a00.x, a10.x, a01.x, a11.x);
            *(float4*)(so + stsA[1]) = make_float4(a00.y, a10.y, a01.y, a11.y);
            *(float4*)(so + stsA[2]) = make_float4(a00.z, a10.z, a01.z, a11.z);
            *(float4*)(so + stsA[3]) = make_float4(a00.w, a10.w, a01.w, a11.w);
            *(float4*)(so + stsB)     = make_float4(bb0.x, bb1.x, bb0.y, bb1.y);
            *(float4*)(so + stsB + 4) = make_float4(bb0.z, bb1.z, bb0.w, bb1.w);
        }
    }
    __syncthreads();

    // ---------- stage scores to smem (expert quad jv of row r at slot jv ^ (r&15)) ----------
    {
        const int r0 = cmi * 16 + cg;
        const int r1 = r0 + 8;
        const int pos = (ct & 1) * 2;
        #pragma unroll
        for (int ni = 0; ni < 8; ni++) {
            const int jv = ni * 2 + (ct >> 1);
            *(float2*)(sm + r0 * 64 + ((jv ^ cg) * 4 + pos))       = make_float2(acc[ni][0], acc[ni][1]);
            *(float2*)(sm + r1 * 64 + ((jv ^ (cg + 8)) * 4 + pos)) = make_float2(acc[ni][2], acc[ni][3]);
        }
    }
    if (tid < NEXP) sm[8704 + tid] = bias[tid];
    int* flag_list = (int*)(sm + 8896);
    int* flag_cnt  = (int*)(sm + 9024);
    if (tid == 0) *flag_cnt = 0;
    __syncthreads();

    // ---------- per-token top-9 + gap check + masked softmax ----------
    if (tid < BM) {
        const int r = tid;
        float sc[64];
        #pragma unroll
        for (int jj = 0; jj < 16; jj++) {
            const int slot = jj ^ (r & 15);
            float4 v  = *(const float4*)(sm + r * 64 + slot * 4);
            float4 bv = *(const float4*)(sm + 8704 + jj * 4);
            sc[jj * 4 + 0] = v.x + bv.x;
            sc[jj * 4 + 1] = v.y + bv.y;
            sc[jj * 4 + 2] = v.z + bv.z;
            sc[jj * 4 + 3] = v.w + bv.w;
        }

        float vals[TOPK + 1];
        int   idxs[TOPK + 1];
        #pragma unroll
        for (int i = 0; i <= TOPK; i++) { vals[i] = -INFINITY; idxs[i] = 0; }
        #pragma unroll
        for (int j = 0; j < NEXP; j++) {
            float s = sc[j];
            if (s > vals[TOPK]) {                  // strict > : ties keep lower index
                vals[TOPK] = s; idxs[TOPK] = j;
                #pragma unroll
                for (int q = TOPK; q > 0; q--) {
                    if (vals[q] > vals[q - 1]) {
                        float tv = vals[q]; vals[q] = vals[q - 1]; vals[q - 1] = tv;
                        int   ti = idxs[q]; idxs[q] = idxs[q - 1]; idxs[q - 1] = ti;
                    }
                }
            }
        }

        float gmin = vals[0] - vals[1];
        #pragma unroll
        for (int i = 1; i <= TOPK - 1; i++) gmin = fminf(gmin, vals[i] - vals[i + 1]);
        gmin = fminf(gmin, vals[TOPK - 1] - vals[TOPK]);   // rank8 vs rank9 (set boundary)

        if (gmin < DELTA) {
            int p = atomicAdd(flag_cnt, 1);
            flag_list[p] = r;                      // defer to exact fp64 path
        } else {
            const float mx   = fmaxf(vals[0], 0.f);
            const float base = expf(-mx);
            float den = (float)(NEXP - TOPK) * base;
            float ev[TOPK];
            #pragma unroll
            for (int i = 0; i < TOPK; i++) { ev[i] = expf(vals[i] - mx); den += ev[i]; }
            const float inv = 1.f / den;
            const float bz  = base * inv;

            const int token = m0 + r;
            float* orow = out + (size_t)token * NEXP;
            #pragma unroll
            for (int j = 0; j < NEXP; j += 4) {
                float4 v; v.x = bz; v.y = bz; v.z = bz; v.w = bz;
                *(float4*)(orow + j) = v;
            }
            #pragma unroll
            for (int i = 0; i < TOPK; i++)
                orow[idxs[i]] = ev[i] * inv;

            if (write_idx) {
                float* oi = out + (size_t)M * NEXP + (size_t)token * TOPK;
                #pragma unroll
                for (int i = 0; i < TOPK; i++) oi[i] = (float)idxs[i];
            }
        }
    }
    __syncthreads();

    // ---------- exact fp64 rescore for near-tie tokens (rare) ----------
    const int nflag = *flag_cnt;
    double* dsc = (double*)(sm + 8768);
    for (int t = 0; t < nflag; t++) {
        const int r = flag_list[t];
        const float* xrow = X + (size_t)(m0 + r) * EMBED;
        const int e  = wid * 8 + (lane >> 2);      // expert 0..63
        const int ls = lane & 3;
        const float* wrow = W + (size_t)e * EMBED;
        double s = 0.0;
        for (int k = ls; k < EMBED; k += 4)
            s += (double)__ldg(xrow + k) * (double)__ldg(wrow + k);
        s += __shfl_xor_sync(0xFFFFFFFFu, s, 1);
        s += __shfl_xor_sync(0xFFFFFFFFu, s, 2);
        if (ls == 0) dsc[e] = s + (double)sm[8704 + e];
        __syncthreads();

        if (tid == 0) {
            double vals[TOPK];
            int    idxs[TOPK];
            #pragma unroll
            for (int i = 0; i < TOPK; i++) { vals[i] = -1e300; idxs[i] = 0; }
            for (int j = 0; j < NEXP; j++) {
                double s2 = dsc[j];
                if (s2 > vals[TOPK - 1]) {
                    vals[TOPK - 1] = s2; idxs[TOPK - 1] = j;
                    #pragma unroll
                    for (int q = TOPK - 1; q > 0; q--) {
                        if (vals[q] > vals[q - 1]) {
                            double tv = vals[q]; vals[q] = vals[q - 1]; vals[q - 1] = tv;
                            int    ti = idxs[q]; idxs[q] = idxs[q - 1]; idxs[q - 1] = ti;
                        }
                    }
                }
            }
            const double mx   = fmax(vals[0], 0.0);
            const double base = exp(-mx);
            double den = (double)(NEXP - TOPK) * base;
            double ev[TOPK];
            #pragma unroll
            for (int i = 0; i < TOPK; i++) { ev[i] = exp(vals[i] - mx); den += ev[i]; }
            const double inv = 1.0 / den;
            const float  bz  = (float)(base * inv);

            const int token = m0 + r;
            float* orow = out + (size_t)token * NEXP;
            for (int j = 0; j < NEXP; j++) orow[j] = bz;
            #pragma unroll
            for (int i = 0; i < TOPK; i++)
                orow[idxs[i]] = (float)(ev[i] * inv);

            if (write_idx) {
                float* oi = out + (size_t)M * NEXP + (size_t)token * TOPK;
                #pragma unroll
                for (int i = 0; i < TOPK; i++) oi[i] = (float)idxs[i];
            }
        }
        __syncthreads();
    }
}

extern "C" void kernel_launch(void* const* d_in, const int* in_sizes, int n_in,
                              void* d_out, int out_size) {
    const float* X = (const float*)d_in[0];
    const float* W = (const float*)d_in[1];
    const float* b = (const float*)d_in[2];
    int M = in_sizes[0] / EMBED;                        // 32768 tokens
    int write_idx = (out_size >= M * (NEXP + TOPK)) ? 1 : 0;
    router_mma<<<M / BM, 256>>>(X, W, b, (float*)d_out, M, write_idx);
}

// round 8
// speedup vs baseline: 3.8817x; 3.8817x over previous
#include <cuda_runtime.h>
#include <cstdint>
#include <math.h>

#define EMBED   2048
#define NEXP    64
#define TOPK    8
#define BM      128
#define BK      32
#define NP      (BK / 2)          // 16 k-pairs per chunk
#define NCHUNK  (EMBED / BK)      // 64
#define STAGE_F 6144              // floats/stage: A 16 KB (4096f) + B 8 KB (2048f)
#define BOFF    4096              // B offset within stage (floats)

typedef unsigned long long ull;

__device__ __forceinline__ uint32_t smem_u32(const void* p) {
    uint32_t a;
    asm("{ .reg .u64 t; cvta.to.shared.u64 t, %1; cvt.u32.u64 %0, t; }" : "=r"(a) : "l"(p));
    return a;
}
// packed dual-fp32 FMA (Blackwell f32x2 pipe, full fp32 per lane)
__device__ __forceinline__ void fma2(ull& c, ull a, ull b) {
    asm("fma.rn.f32x2 %0, %1, %2, %0;" : "+l"(c) : "l"(a), "l"(b));
}
__device__ __forceinline__ void cpa8(uint32_t dst, const void* src) {
    asm volatile("cp.async.ca.shared.global [%0], [%1], 8;" :: "r"(dst), "l"(src));
}
__device__ __forceinline__ float accf(ull v) {   // lo + hi halves
    return __uint_as_float((uint32_t)v) + __uint_as_float((uint32_t)(v >> 32));
}

__global__ __launch_bounds__(256, 2)
void router_f32x2(const float* __restrict__ X,
                  const float* __restrict__ W,
                  const float* __restrict__ bias,
                  float* __restrict__ out,
                  int M, int write_idx)
{
    __shared__ float sm[2 * STAGE_F];      // 48 KB; reused for scores after mainloop
    const uint32_t smb = smem_u32(sm);
    const int tid = threadIdx.x;
    const int m0  = blockIdx.x * BM;
    const int tg  = tid >> 4;              // token group: tokens tg*8 .. +7
    const int eg  = tid & 15;              // expert group: experts eg*4 .. +3

    // ---- cp.async issue for chunk c into stage s ----
    const float* Xb = X + (size_t)m0 * EMBED;
    auto issue = [&](int c, int s) {
        const int k0 = c * BK;
        const uint32_t sb = smb + s * (STAGE_F * 4);
        #pragma unroll
        for (int j = 0; j < 8; j++) {                  // A: 128 tok x 16 pairs
            const int ci = tid + j * 256;
            const int t = ci >> 4, p = ci & 15;
            cpa8(sb + (p * 256 + t * 2) * 4, Xb + (size_t)t * EMBED + k0 + p * 2);
        }
        #pragma unroll
        for (int j = 0; j < 4; j++) {                  // B: 64 exp x 16 pairs
            const int ci = tid + j * 256;
            const int e = ci >> 4, p = ci & 15;
            cpa8(sb + (BOFF + p * 128 + e * 2) * 4, W + (size_t)e * EMBED + k0 + p * 2);
        }
    };

    ull acc[8][4];
    #pragma unroll
    for (int i = 0; i < 8; i++)
        #pragma unroll
        for (int j = 0; j < 4; j++) acc[i][j] = 0ull;

    issue(0, 0);
    asm volatile("cp.async.commit_group;");

    for (int c = 0; c < NCHUNK; c++) {
        if (c + 1 < NCHUNK) {
            issue(c + 1, (c + 1) & 1);
            asm volatile("cp.async.commit_group;");
            asm volatile("cp.async.wait_group 1;");
        } else {
            asm volatile("cp.async.wait_group 0;");
        }
        __syncthreads();                   // stage c visible

        const float* sb = sm + (c & 1) * STAGE_F;
        #pragma unroll 4
        for (int p = 0; p < NP; p++) {
            ulonglong2 au[4], bu[2];
            #pragma unroll
            for (int i = 0; i < 4; i++)
                au[i] = *(const ulonglong2*)(sb + p * 256 + tg * 16 + i * 4);
            #pragma unroll
            for (int j = 0; j < 2; j++)
                bu[j] = *(const ulonglong2*)(sb + BOFF + p * 128 + eg * 8 + j * 4);
            #pragma unroll
            for (int i = 0; i < 4; i++) {
                #pragma unroll
                for (int j = 0; j < 2; j++) {
                    fma2(acc[2 * i    ][2 * j    ], au[i].x, bu[j].x);
                    fma2(acc[2 * i    ][2 * j + 1], au[i].x, bu[j].y);
                    fma2(acc[2 * i + 1][2 * j    ], au[i].y, bu[j].x);
                    fma2(acc[2 * i + 1][2 * j + 1], au[i].y, bu[j].y);
                }
            }
        }
        __syncthreads();                   // stage c consumed; next issue may overwrite
    }

    // ---------- stage scores (row stride 68) ----------
    #pragma unroll
    for (int tt = 0; tt < 8; tt++) {
        float4 v;
        v.x = accf(acc[tt][0]); v.y = accf(acc[tt][1]);
        v.z = accf(acc[tt][2]); v.w = accf(acc[tt][3]);
        *(float4*)(sm + (tg * 8 + tt) * 68 + eg * 4) = v;
    }
    if (tid < NEXP) sm[8704 + tid] = bias[tid];
    __syncthreads();

    // ---------- per-token top-8 + masked softmax (R1-verified) ----------
    if (tid < BM) {
        const int r = tid;
        float sc[64];
        #pragma unroll
        for (int jj = 0; jj < 16; jj++) {
            float4 v  = *(const float4*)(sm + r * 68 + jj * 4);
            float4 bv = *(const float4*)(sm + 8704 + jj * 4);
            sc[jj * 4 + 0] = v.x + bv.x;
            sc[jj * 4 + 1] = v.y + bv.y;
            sc[jj * 4 + 2] = v.z + bv.z;
            sc[jj * 4 + 3] = v.w + bv.w;
        }

        float vals[TOPK];
        int   idxs[TOPK];
        #pragma unroll
        for (int i = 0; i < TOPK; i++) { vals[i] = -INFINITY; idxs[i] = 0; }
        #pragma unroll
        for (int j = 0; j < NEXP; j++) {
            float s = sc[j];
            if (s > vals[TOPK - 1]) {            // strict > : ties keep lower index
                vals[TOPK - 1] = s; idxs[TOPK - 1] = j;
                #pragma unroll
                for (int q = TOPK - 1; q > 0; q--) {
                    if (vals[q] > vals[q - 1]) {
                        float tv = vals[q]; vals[q] = vals[q - 1]; vals[q - 1] = tv;
                        int   ti = idxs[q]; idxs[q] = idxs[q - 1]; idxs[q - 1] = ti;
                    }
                }
            }
        }

        const float mx   = fmaxf(vals[0], 0.f);
        const float base = expf(-mx);
        float den = (float)(NEXP - TOPK) * base;
        float ev[TOPK];
        #pragma unroll
        for (int i = 0; i < TOPK; i++) { ev[i] = expf(vals[i] - mx); den += ev[i]; }
        const float inv = 1.f / den;
        const float bz  = base * inv;

        const int token = m0 + r;
        float* orow = out + (size_t)token * NEXP;
        #pragma unroll
        for (int j = 0; j < NEXP; j += 4) {
            float4 v; v.x = bz; v.y = bz; v.z = bz; v.w = bz;
            *(float4*)(orow + j) = v;
        }
        #pragma unroll
        for (int i = 0; i < TOPK; i++)
            orow[idxs[i]] = ev[i] * inv;

        if (write_idx) {
            float* oi = out + (size_t)M * NEXP + (size_t)token * TOPK;
            #pragma unroll
            for (int i = 0; i < TOPK; i++) oi[i] = (float)idxs[i];
        }
    }
}

extern "C" void kernel_launch(void* const* d_in, const int* in_sizes, int n_in,
                              void* d_out, int out_size) {
    const float* X = (const float*)d_in[0];
    const float* W = (const float*)d_in[1];
    const float* b = (const float*)d_in[2];
    int M = in_sizes[0] / EMBED;                        // 32768 tokens
    int write_idx = (out_size >= M * (NEXP + TOPK)) ? 1 : 0;
    router_f32x2<<<M / BM, 256>>>(X, W, b, (float*)d_out, M, write_idx);
}

// round 9
// speedup vs baseline: 4.7448x; 1.2224x over previous
#include <cuda_runtime.h>
#include <cstdint>
#include <math.h>

#define EMBED   2048
#define NEXP    64
#define TOPK    8
#define BM      128
#define BK      32
#define NP      (BK / 2)          // 16 k-pairs per chunk
#define NCHUNK  (EMBED / BK)      // 64
#define STAGE_F 6144              // floats/stage: A 16 KB (4096f) + B 8 KB (2048f)
#define BOFF    4096              // B offset within stage (floats)

typedef unsigned long long ull;

__device__ __forceinline__ uint32_t smem_u32(const void* p) {
    uint32_t a;
    asm("{ .reg .u64 t; cvta.to.shared.u64 t, %1; cvt.u32.u64 %0, t; }" : "=r"(a) : "l"(p));
    return a;
}
// packed dual-fp32 FMA (Blackwell f32x2 pipe, full fp32 per lane)
__device__ __forceinline__ void fma2(ull& c, ull a, ull b) {
    asm("fma.rn.f32x2 %0, %1, %2, %0;" : "+l"(c) : "l"(a), "l"(b));
}
__device__ __forceinline__ void cpa8(uint32_t dst, const void* src) {
    asm volatile("cp.async.ca.shared.global [%0], [%1], 8;" :: "r"(dst), "l"(src));
}
__device__ __forceinline__ float accf(ull v) {   // lo + hi halves
    return __uint_as_float((uint32_t)v) + __uint_as_float((uint32_t)(v >> 32));
}

__global__ __launch_bounds__(256, 2)
void router_f32x2(const float* __restrict__ X,
                  const float* __restrict__ W,
                  const float* __restrict__ bias,
                  float* __restrict__ out,
                  int M, int write_idx)
{
    __shared__ float sm[2 * STAGE_F];      // 48 KB; reused for scores after mainloop
    const uint32_t smb = smem_u32(sm);
    const int tid  = threadIdx.x;
    const int m0   = blockIdx.x * BM;
    const int tg   = tid >> 5;             // warp-uniform: tokens tg*16 .. +15
    const int eg   = tid & 31;             // experts 2*eg, 2*eg+1

    // ---- cp.async issue for chunk c into stage s ----
    // A layout: per pair p (row of 256 floats): 64 units of 16B; unit v swizzled v^p.
    //   unit v holds tokens (2v, 2v+1) of pair p.
    // B layout: per pair p (row of 128 floats): 32 units of 16B; unit u swizzled u^(p&7).
    //   unit u holds experts (2u, 2u+1) of pair p.
    const float* Xb = X + (size_t)m0 * EMBED;
    auto issue = [&](int c, int s) {
        const int k0 = c * BK;
        const uint32_t sb = smb + s * (STAGE_F * 4);
        #pragma unroll
        for (int j = 0; j < 8; j++) {                  // A: 128 tok x 16 pairs (8B each)
            const int ci = tid + j * 256;
            const int t = ci >> 4, p = ci & 15;
            const uint32_t off = (uint32_t)(p * 256 + (((t >> 1) ^ p) * 4) + (t & 1) * 2);
            cpa8(sb + off * 4, Xb + (size_t)t * EMBED + k0 + p * 2);
        }
        #pragma unroll
        for (int j = 0; j < 4; j++) {                  // B: 64 exp x 16 pairs (8B each)
            const int ci = tid + j * 256;
            const int e = ci >> 4, p = ci & 15;
            const uint32_t off = (uint32_t)(BOFF + p * 128 + (((e >> 1) ^ (p & 7)) * 4) + (e & 1) * 2);
            cpa8(sb + off * 4, W + (size_t)e * EMBED + k0 + p * 2);
        }
    };

    ull acc[16][2];
    #pragma unroll
    for (int i = 0; i < 16; i++) { acc[i][0] = 0ull; acc[i][1] = 0ull; }

    issue(0, 0);
    asm volatile("cp.async.commit_group;");

    for (int c = 0; c < NCHUNK; c++) {
        if (c + 1 < NCHUNK) {
            issue(c + 1, (c + 1) & 1);
            asm volatile("cp.async.commit_group;");
            asm volatile("cp.async.wait_group 1;");
        } else {
            asm volatile("cp.async.wait_group 0;");
        }
        __syncthreads();                   // stage c visible

        const float* sb = sm + (c & 1) * STAGE_F;
        #pragma unroll 2
        for (int p = 0; p < NP; p++) {
            // B: one conflict-free LDS.128 (lanes are a permutation of the 32 units)
            const ulonglong2 bu = *(const ulonglong2*)(sb + BOFF + p * 128 + ((eg ^ (p & 7)) * 4));
            // A: 8 broadcast LDS.128 (whole warp reads the same unit)
            ulonglong2 au[8];
            #pragma unroll
            for (int i = 0; i < 8; i++)
                au[i] = *(const ulonglong2*)(sb + p * 256 + (((tg * 8 + i) ^ p) * 4));
            #pragma unroll
            for (int i = 0; i < 8; i++) {
                fma2(acc[2 * i    ][0], au[i].x, bu.x);
                fma2(acc[2 * i    ][1], au[i].x, bu.y);
                fma2(acc[2 * i + 1][0], au[i].y, bu.x);
                fma2(acc[2 * i + 1][1], au[i].y, bu.y);
            }
        }
        __syncthreads();                   // stage c consumed; next issue may overwrite
    }

    // ---------- stage scores (row stride 68) ----------
    #pragma unroll
    for (int tt = 0; tt < 16; tt++) {
        float2 v;
        v.x = accf(acc[tt][0]);            // expert 2*eg
        v.y = accf(acc[tt][1]);            // expert 2*eg+1
        *(float2*)(sm + (tg * 16 + tt) * 68 + eg * 2) = v;
    }
    if (tid < NEXP) sm[8704 + tid] = bias[tid];
    __syncthreads();

    // ---------- per-token top-8 + masked softmax (R1/R8-verified) ----------
    if (tid < BM) {
        const int r = tid;
        float sc[64];
        #pragma unroll
        for (int jj = 0; jj < 16; jj++) {
            float4 v  = *(const float4*)(sm + r * 68 + jj * 4);
            float4 bv = *(const float4*)(sm + 8704 + jj * 4);
            sc[jj * 4 + 0] = v.x + bv.x;
            sc[jj * 4 + 1] = v.y + bv.y;
            sc[jj * 4 + 2] = v.z + bv.z;
            sc[jj * 4 + 3] = v.w + bv.w;
        }

        float vals[TOPK];
        int   idxs[TOPK];
        #pragma unroll
        for (int i = 0; i < TOPK; i++) { vals[i] = -INFINITY; idxs[i] = 0; }
        #pragma unroll
        for (int j = 0; j < NEXP; j++) {
            float s = sc[j];
            if (s > vals[TOPK - 1]) {            // strict > : ties keep lower index
                vals[TOPK - 1] = s; idxs[TOPK - 1] = j;
                #pragma unroll
                for (int q = TOPK - 1; q > 0; q--) {
                    if (vals[q] > vals[q - 1]) {
                        float tv = vals[q]; vals[q] = vals[q - 1]; vals[q - 1] = tv;
                        int   ti = idxs[q]; idxs[q] = idxs[q - 1]; idxs[q - 1] = ti;
                    }
                }
            }
        }

        const float mx   = fmaxf(vals[0], 0.f);
        const float base = expf(-mx);
        float den = (float)(NEXP - TOPK) * base;
        float ev[TOPK];
        #pragma unroll
        for (int i = 0; i < TOPK; i++) { ev[i] = expf(vals[i] - mx); den += ev[i]; }
        const float inv = 1.f / den;
        const float bz  = base * inv;

        const int token = m0 + r;
        float* orow = out + (size_t)token * NEXP;
        #pragma unroll
        for (int j = 0; j < NEXP; j += 4) {
            float4 v; v.x = bz; v.y = bz; v.z = bz; v.w = bz;
            *(float4*)(orow + j) = v;
        }
        #pragma unroll
        for (int i = 0; i < TOPK; i++)
            orow[idxs[i]] = ev[i] * inv;

        if (write_idx) {
            float* oi = out + (size_t)M * NEXP + (size_t)token * TOPK;
            #pragma unroll
            for (int i = 0; i < TOPK; i++) oi[i] = (float)idxs[i];
        }
    }
}

extern "C" void kernel_launch(void* const* d_in, const int* in_sizes, int n_in,
                              void* d_out, int out_size) {
    const float* X = (const float*)d_in[0];
    const float* W = (const float*)d_in[1];
    const float* b = (const float*)d_in[2];
    int M = in_sizes[0] / EMBED;                        // 32768 tokens
    int write_idx = (out_size >= M * (NEXP + TOPK)) ? 1 : 0;
    router_f32x2<<<M / BM, 256>>>(X, W, b, (float*)d_out, M, write_idx);
}

// round 10
// speedup vs baseline: 6.6018x; 1.3914x over previous
#include <cuda_runtime.h>
#include <cstdint>
#include <math.h>

#define EMBED   2048
#define NEXP    64
#define TOPK    8
#define BM      128
#define BK      32
#define NCHUNK  (EMBED / BK)      // 64
#define STAGE_F 6144              // floats/stage: A 4096 + B 2048
#define BOFF    4096              // B offset within stage (floats)

typedef unsigned long long ull;

__device__ __forceinline__ uint32_t smem_u32(const void* p) {
    uint32_t a;
    asm("{ .reg .u64 t; cvta.to.shared.u64 t, %1; cvt.u32.u64 %0, t; }" : "=r"(a) : "l"(p));
    return a;
}
// packed dual-fp32 FMA (Blackwell f32x2 pipe, full fp32 per lane)
__device__ __forceinline__ void fma2(ull& c, ull a, ull b) {
    asm("fma.rn.f32x2 %0, %1, %2, %0;" : "+l"(c) : "l"(a), "l"(b));
}
__device__ __forceinline__ void cpa8(uint32_t dst, const void* src) {
    asm volatile("cp.async.ca.shared.global [%0], [%1], 8;" :: "r"(dst), "l"(src));
}
__device__ __forceinline__ float accf(ull v) {   // lo + hi halves
    return __uint_as_float((uint32_t)v) + __uint_as_float((uint32_t)(v >> 32));
}

__global__ __launch_bounds__(256, 2)
void router_f32x2(const float* __restrict__ X,
                  const float* __restrict__ W,
                  const float* __restrict__ bias,
                  float* __restrict__ out,
                  int M, int write_idx)
{
    __shared__ float sm[2 * STAGE_F];      // 48 KB; reused for scores after mainloop
    const uint32_t smb = smem_u32(sm);
    const int tid = threadIdx.x;
    const int m0  = blockIdx.x * BM;
    const int tg  = tid >> 5;              // warp-uniform: tokens tg*16 .. +15
    const int eg  = tid & 31;              // experts 2*eg, 2*eg+1

    // ---- hoisted producer addressing ----
    // A layout: [t][k] linear — token row = 32 floats (128B). STS conflict-free
    //   (16 lanes write consecutive 8B within one row). Consumer A = broadcast.
    // B layout: [p][e] 16B units, unit u holds experts (2u,2u+1), swizzled u^(p&7).
    const float* xsrc[8]; uint32_t adst[8];
    #pragma unroll
    for (int j = 0; j < 8; j++) {
        const int ci = tid + j * 256;      // 0..2047
        const int t = ci >> 4, p = ci & 15;
        xsrc[j] = X + (size_t)(m0 + t) * EMBED + p * 2;
        adst[j] = (uint32_t)(t * 32 + p * 2) * 4;
    }
    const float* wsrc[4]; uint32_t bdst[4];
    #pragma unroll
    for (int j = 0; j < 4; j++) {
        const int ci = tid + j * 256;      // 0..1023
        const int e = ci >> 4, p = ci & 15;
        wsrc[j] = W + (size_t)e * EMBED + p * 2;
        bdst[j] = (uint32_t)(BOFF + p * 128 + (((e >> 1) ^ (p & 7)) * 4) + (e & 1) * 2) * 4;
    }

    auto issue = [&](int c, int s) {
        const int k0 = c * BK;
        const uint32_t sb = smb + s * (STAGE_F * 4);
        #pragma unroll
        for (int j = 0; j < 8; j++) cpa8(sb + adst[j], xsrc[j] + k0);
        #pragma unroll
        for (int j = 0; j < 4; j++) cpa8(sb + bdst[j], wsrc[j] + k0);
    };

    ull acc[16][2];
    #pragma unroll
    for (int i = 0; i < 16; i++) { acc[i][0] = 0ull; acc[i][1] = 0ull; }

    issue(0, 0);
    asm volatile("cp.async.commit_group;");

    for (int c = 0; c < NCHUNK; c++) {
        if (c + 1 < NCHUNK) {
            issue(c + 1, (c + 1) & 1);
            asm volatile("cp.async.commit_group;");
            asm volatile("cp.async.wait_group 1;");
        } else {
            asm volatile("cp.async.wait_group 0;");
        }
        __syncthreads();                   // stage c visible

        const float* Ab = sm + (c & 1) * STAGE_F + tg * 512;   // warp's 16 token rows
        const float* Bb = sm + (c & 1) * STAGE_F + BOFF;
        #pragma unroll
        for (int pp = 0; pp < 8; pp++) {   // 2 k-pairs per step
            // B: two conflict-free LDS.128 (lane permutation within 512B row)
            const ulonglong2 bu0 = *(const ulonglong2*)(Bb + (2 * pp)     * 128 + ((eg ^ ((2 * pp)     & 7)) * 4));
            const ulonglong2 bu1 = *(const ulonglong2*)(Bb + (2 * pp + 1) * 128 + ((eg ^ ((2 * pp + 1) & 7)) * 4));
            #pragma unroll
            for (int tt = 0; tt < 16; tt++) {
                // broadcast LDS.128: pairs 2pp (au.x) and 2pp+1 (au.y) of token tt
                const ulonglong2 au = *(const ulonglong2*)(Ab + tt * 32 + pp * 4);
                fma2(acc[tt][0], au.x, bu0.x);   // exp 2eg,   pair 2pp
                fma2(acc[tt][1], au.x, bu0.y);   // exp 2eg+1, pair 2pp
                fma2(acc[tt][0], au.y, bu1.x);   // exp 2eg,   pair 2pp+1
                fma2(acc[tt][1], au.y, bu1.y);   // exp 2eg+1, pair 2pp+1
            }
        }
        __syncthreads();                   // stage c consumed; next issue may overwrite
    }

    // ---------- stage scores (row stride 68) ----------
    #pragma unroll
    for (int tt = 0; tt < 16; tt++) {
        float2 v;
        v.x = accf(acc[tt][0]);            // expert 2*eg
        v.y = accf(acc[tt][1]);            // expert 2*eg+1
        *(float2*)(sm + (tg * 16 + tt) * 68 + eg * 2) = v;
    }
    if (tid < NEXP) sm[8704 + tid] = bias[tid];
    __syncthreads();

    // ---------- per-token top-8 + masked softmax (verified R1/R8/R9) ----------
    if (tid < BM) {
        const int r = tid;
        float sc[64];
        #pragma unroll
        for (int jj = 0; jj < 16; jj++) {
            float4 v  = *(const float4*)(sm + r * 68 + jj * 4);
            float4 bv = *(const float4*)(sm + 8704 + jj * 4);
            sc[jj * 4 + 0] = v.x + bv.x;
            sc[jj * 4 + 1] = v.y + bv.y;
            sc[jj * 4 + 2] = v.z + bv.z;
            sc[jj * 4 + 3] = v.w + bv.w;
        }

        float vals[TOPK];
        int   idxs[TOPK];
        #pragma unroll
        for (int i = 0; i < TOPK; i++) { vals[i] = -INFINITY; idxs[i] = 0; }
        #pragma unroll
        for (int j = 0; j < NEXP; j++) {
            float s = sc[j];
            if (s > vals[TOPK - 1]) {            // strict > : ties keep lower index
                vals[TOPK - 1] = s; idxs[TOPK - 1] = j;
                #pragma unroll
                for (int q = TOPK - 1; q > 0; q--) {
                    if (vals[q] > vals[q - 1]) {
                        float tv = vals[q]; vals[q] = vals[q - 1]; vals[q - 1] = tv;
                        int   ti = idxs[q]; idxs[q] = idxs[q - 1]; idxs[q - 1] = ti;
                    }
                }
            }
        }

        const float mx   = fmaxf(vals[0], 0.f);
        const float base = expf(-mx);
        float den = (float)(NEXP - TOPK) * base;
        float ev[TOPK];
        #pragma unroll
        for (int i = 0; i < TOPK; i++) { ev[i] = expf(vals[i] - mx); den += ev[i]; }
        const float inv = 1.f / den;
        const float bz  = base * inv;

        const int token = m0 + r;
        float* orow = out + (size_t)token * NEXP;
        #pragma unroll
        for (int j = 0; j < NEXP; j += 4) {
            float4 v; v.x = bz; v.y = bz; v.z = bz; v.w = bz;
            *(float4*)(orow + j) = v;
        }
        #pragma unroll
        for (int i = 0; i < TOPK; i++)
            orow[idxs[i]] = ev[i] * inv;

        if (write_idx) {
            float* oi = out + (size_t)M * NEXP + (size_t)token * TOPK;
            #pragma unroll
            for (int i = 0; i < TOPK; i++) oi[i] = (float)idxs[i];
        }
    }
}

extern "C" void kernel_launch(void* const* d_in, const int* in_sizes, int n_in,
                              void* d_out, int out_size) {
    const float* X = (const float*)d_in[0];
    const float* W = (const float*)d_in[1];
    const float* b = (const float*)d_in[2];
    int M = in_sizes[0] / EMBED;                        // 32768 tokens
    int write_idx = (out_size >= M * (NEXP + TOPK)) ? 1 : 0;
    router_f32x2<<<M / BM, 256>>>(X, W, b, (float*)d_out, M, write_idx);
}